// round 16
// baseline (speedup 1.0000x reference)
#include <cuda_runtime.h>
#include <cuda_fp16.h>
#include <cstdint>

#define N_NODES 100000
#define E_EDGES 640000

// ---------------------------------------------------------------------------
// Global scratch
// ---------------------------------------------------------------------------
__device__ __half g_xw_h[(size_t)N_NODES * 128];   // x @ Wn (fp16 storage)
__device__ __half g_axw_h[(size_t)N_NODES * 128];  // fp16 shadow of axw
__device__ int    g_idx64;                          // edge_index dtype flag
__device__ int    g_cnt[N_NODES];                   // per-dst degree
__device__ int    g_off[N_NODES];                   // exclusive offsets -> ends
__device__ int    g_bucket[E_EDGES];                // src ids grouped by dst

// ---------------------------------------------------------------------------
// Helpers
// ---------------------------------------------------------------------------
__device__ __forceinline__ uint32_t smem_u32(const void* p) {
    uint32_t a;
    asm("{ .reg .u64 t; cvta.to.shared.u64 t, %1; cvt.u32.u64 %0, t; }"
        : "=r"(a) : "l"(p));
    return a;
}

__device__ __forceinline__ void mma_f16(float* d, const uint32_t* a, const uint32_t* b) {
    asm volatile(
        "mma.sync.aligned.m16n8k16.row.col.f32.f16.f16.f32 "
        "{%0,%1,%2,%3}, {%4,%5,%6,%7}, {%8,%9}, {%0,%1,%2,%3};"
        : "+f"(d[0]), "+f"(d[1]), "+f"(d[2]), "+f"(d[3])
        : "r"(a[0]), "r"(a[1]), "r"(a[2]), "r"(a[3]), "r"(b[0]), "r"(b[1]));
}

__device__ __forceinline__ void ldsm_x4(uint32_t* r, uint32_t addr) {
    asm volatile("ldmatrix.sync.aligned.m8n8.x4.shared.b16 {%0,%1,%2,%3}, [%4];"
                 : "=r"(r[0]), "=r"(r[1]), "=r"(r[2]), "=r"(r[3]) : "r"(addr));
}
__device__ __forceinline__ void ldsm_x4t(uint32_t* r, uint32_t addr) {
    asm volatile("ldmatrix.sync.aligned.m8n8.x4.trans.shared.b16 {%0,%1,%2,%3}, [%4];"
                 : "=r"(r[0]), "=r"(r[1]), "=r"(r[2]), "=r"(r[3]) : "r"(addr));
}

__device__ __forceinline__ void cp_async16(uint32_t smem_dst, const void* gmem_src) {
    asm volatile("cp.async.ca.shared.global [%0], [%1], 16;"
                 :: "r"(smem_dst), "l"(gmem_src) : "memory");
}

__device__ __forceinline__ int r0_expr(int wr, int lane) { return wr * 32 + (lane >> 2); }

// ---------------------------------------------------------------------------
// detect idx dtype + zero the degree counters
// ---------------------------------------------------------------------------
__global__ __launch_bounds__(256)
void detect_zero_kernel(const void* __restrict__ eidx) {
    int i = blockIdx.x * blockDim.x + threadIdx.x;
    if (i < N_NODES) g_cnt[i] = 0;
    if (i == 0) {
        const unsigned long long* p = (const unsigned long long*)eidx;
        int ok = 1;
        #pragma unroll 1
        for (int j = 0; j < 64; j++)
            if (p[j] >= (unsigned long long)N_NODES) { ok = 0; break; }
        g_idx64 = ok;
    }
}

__device__ __forceinline__ long ld_idx(const void* __restrict__ p, long i) {
    if (g_idx64) return (long)((const long long*)p)[i];
    return (long)((const int*)p)[i];
}

// ---------------------------------------------------------------------------
// CSR build: histogram -> scan -> fill
// ---------------------------------------------------------------------------
__global__ __launch_bounds__(256)
void hist_kernel(const void* __restrict__ eidx) {
    int e = blockIdx.x * blockDim.x + threadIdx.x;
    if (e < E_EDGES) {
        int dst = (int)ld_idx(eidx, (long)E_EDGES + e);
        atomicAdd(&g_cnt[dst], 1);
    }
}

// single block, 1024 threads: exclusive prefix of g_cnt into g_off
__global__ __launch_bounds__(1024)
void scan_kernel() {
    __shared__ int part[1024];
    const int t = threadIdx.x;
    const int CH = (N_NODES + 1023) / 1024;    // 98
    const int base = t * CH;
    int s = 0;
    #pragma unroll 1
    for (int j = 0; j < CH; j++) {
        int i = base + j;
        if (i < N_NODES) s += g_cnt[i];
    }
    part[t] = s;
    __syncthreads();
    // Hillis-Steele inclusive scan
    for (int d = 1; d < 1024; d <<= 1) {
        int v = (t >= d) ? part[t - d] : 0;
        __syncthreads();
        part[t] += v;
        __syncthreads();
    }
    int run = (t == 0) ? 0 : part[t - 1];
    #pragma unroll 1
    for (int j = 0; j < CH; j++) {
        int i = base + j;
        if (i < N_NODES) { g_off[i] = run; run += g_cnt[i]; }
    }
}

// bucket[pos] = src, grouped by dst; g_off becomes per-dst END offsets
__global__ __launch_bounds__(256)
void fill_kernel(const void* __restrict__ eidx) {
    int e = blockIdx.x * blockDim.x + threadIdx.x;
    if (e < E_EDGES) {
        int src = (int)ld_idx(eidx, e);
        int dst = (int)ld_idx(eidx, (long)E_EDGES + e);
        int pos = atomicAdd(&g_off[dst], 1);
        g_bucket[pos] = src;
    }
}

// ---------------------------------------------------------------------------
// Aggregate: warp per node; sum fp16 xw rows in fp32; write axw + shadow.
// No atomics; every axw row written exactly once (no zero-init needed).
// ---------------------------------------------------------------------------
__global__ __launch_bounds__(256)
void aggregate_kernel(const __half* __restrict__ xwh,
                      float* __restrict__ axw, __half* __restrict__ shadow) {
    int w = (blockIdx.x * blockDim.x + threadIdx.x) >> 5;
    int lane = threadIdx.x & 31;
    if (w >= N_NODES) return;
    int n = g_cnt[w];
    int start = g_off[w] - n;          // off holds ends after fill
    float a0 = 0.f, a1 = 0.f, a2 = 0.f, a3 = 0.f;
    int j = 0;
    for (; j + 4 <= n; j += 4) {
        int s0 = g_bucket[start + j + 0];
        int s1 = g_bucket[start + j + 1];
        int s2 = g_bucket[start + j + 2];
        int s3 = g_bucket[start + j + 3];
        uint2 r0 = *(const uint2*)(xwh + (long)s0 * 128 + lane * 4);
        uint2 r1 = *(const uint2*)(xwh + (long)s1 * 128 + lane * 4);
        uint2 r2 = *(const uint2*)(xwh + (long)s2 * 128 + lane * 4);
        uint2 r3 = *(const uint2*)(xwh + (long)s3 * 128 + lane * 4);
        float2 f;
        f = __half22float2(*(__half2*)&r0.x); a0 += f.x; a1 += f.y;
        f = __half22float2(*(__half2*)&r0.y); a2 += f.x; a3 += f.y;
        f = __half22float2(*(__half2*)&r1.x); a0 += f.x; a1 += f.y;
        f = __half22float2(*(__half2*)&r1.y); a2 += f.x; a3 += f.y;
        f = __half22float2(*(__half2*)&r2.x); a0 += f.x; a1 += f.y;
        f = __half22float2(*(__half2*)&r2.y); a2 += f.x; a3 += f.y;
        f = __half22float2(*(__half2*)&r3.x); a0 += f.x; a1 += f.y;
        f = __half22float2(*(__half2*)&r3.y); a2 += f.x; a3 += f.y;
    }
    for (; j < n; j++) {
        int s0 = g_bucket[start + j];
        uint2 r0 = *(const uint2*)(xwh + (long)s0 * 128 + lane * 4);
        float2 f;
        f = __half22float2(*(__half2*)&r0.x); a0 += f.x; a1 += f.y;
        f = __half22float2(*(__half2*)&r0.y); a2 += f.x; a3 += f.y;
    }
    *(float4*)(axw + (long)w * 128 + lane * 4) = make_float4(a0, a1, a2, a3);
    uint2 hs;
    *(__half2*)&hs.x = __floats2half2_rn(a0, a1);
    *(__half2*)&hs.y = __floats2half2_rn(a2, a3);
    *(uint2*)(shadow + (long)w * 128 + lane * 4) = hs;
}

// ---------------------------------------------------------------------------
// xw GEMM: 64-row tiles, 2 CTAs/SM, fp16 output.
// ---------------------------------------------------------------------------
__global__ __launch_bounds__(256, 2)
void gemm_xw_kernel(const float* __restrict__ A, const float* __restrict__ W,
                    __half* __restrict__ C, int M) {
    constexpr int K = 256;
    constexpr int KCH = 2;
    constexpr uint32_t OFF_A = (uint32_t)K * 256;

    extern __shared__ __align__(128) char smem[];
    const uint32_t sb = smem_u32(smem);
    const int tid = threadIdx.x, lane = tid & 31, wid = tid >> 5;
    const int wr = wid & 1, wc = wid >> 1;

    for (int p = tid; p < K * 64; p += 256) {
        int k = p >> 6, n = (p & 63) * 2;
        float2 wv = *(const float2*)(W + (long)k * 128 + n);
        __half2 hp = __floats2half2_rn(wv.x, wv.y);
        uint32_t off = (uint32_t)k * 256 +
                       ((((uint32_t)n >> 3) ^ ((uint32_t)k & 7)) << 4) + ((n & 7) << 1);
        *(__half2*)(smem + off) = hp;
    }

    const int ntiles = (M + 63) >> 6;
    const int G = gridDim.x;
    float2 pref[16];

    auto prefetch = [&](int t, int kc) {
        #pragma unroll
        for (int i = 0; i < 16; i++) {
            int p = i * 256 + tid;
            int r = p >> 6, pc = p & 63;
            long row = (long)t * 64 + r;
            float2 v = make_float2(0.f, 0.f);
            if (row < M) v = __ldcs((const float2*)(A + row * (long)K + kc * 128 + pc * 2));
            pref[i] = v;
        }
    };
    auto store_buf = [&](int b) {
        #pragma unroll
        for (int i = 0; i < 16; i++) {
            int p = i * 256 + tid;
            int r = p >> 6, col = (p & 63) * 2;
            __half2 hp = __floats2half2_rn(pref[i].x, pref[i].y);
            uint32_t off = (uint32_t)r * 256 +
                           ((((uint32_t)col >> 3) ^ ((uint32_t)r & 7)) << 4) +
                           ((col & 7) << 1);
            *(__half2*)(smem + OFF_A + (uint32_t)b * 16384 + off) = hp;
        }
    };

    int tile = blockIdx.x;
    if (tile < ntiles) {
        prefetch(tile, 0);
        store_buf(0);
        prefetch(tile, 1);
    }
    __syncthreads();

    int cur = 0;
    for (; tile < ntiles; tile += G) {
        float acc[2][4][4];
        #pragma unroll
        for (int m = 0; m < 2; m++)
            #pragma unroll
            for (int nb = 0; nb < 4; nb++)
                #pragma unroll
                for (int c = 0; c < 4; c++) acc[m][nb][c] = 0.f;

        for (int kc = 0; kc < KCH; kc++) {
            int nt1 = tile, nkc1 = kc + 1;
            if (nkc1 == KCH) { nkc1 = 0; nt1 = tile + G; }
            if (nt1 < ntiles) store_buf(cur ^ 1);
            int nt2 = nt1, nkc2 = nkc1 + 1;
            if (nkc2 == KCH) { nkc2 = 0; nt2 = nt1 + G; }
            if (nt2 < ntiles) prefetch(nt2, nkc2);

            const uint32_t abase = sb + OFF_A + (uint32_t)cur * 16384;
            #pragma unroll
            for (int s = 0; s < 8; s++) {
                uint32_t a[2][4];
                #pragma unroll
                for (int m = 0; m < 2; m++) {
                    uint32_t r = (uint32_t)(wr * 32 + m * 16 + (lane & 15));
                    uint32_t ch = (uint32_t)(s * 2 + (lane >> 4));
                    ldsm_x4(a[m], abase + r * 256 + (((ch ^ (r & 7)) << 4)));
                }
                uint32_t bh[2][4];
                #pragma unroll
                for (int p4 = 0; p4 < 2; p4++) {
                    uint32_t k = (uint32_t)(kc * 128 + s * 16 + (lane & 15));
                    uint32_t nch = (uint32_t)(wc * 4 + p4 * 2 + (lane >> 4));
                    ldsm_x4t(bh[p4], sb + k * 256 + (((nch ^ (k & 7)) << 4)));
                }
                #pragma unroll
                for (int m = 0; m < 2; m++)
                    #pragma unroll
                    for (int p4 = 0; p4 < 2; p4++)
                        #pragma unroll
                        for (int h = 0; h < 2; h++)
                            mma_f16(acc[m][p4 * 2 + h], a[m], &bh[p4][2 * h]);
            }
            if (kc < KCH - 1) { __syncthreads(); cur ^= 1; }
        }

        #pragma unroll
        for (int j = 0; j < 4; j++) {
            const int m = j >> 1, cp = (j & 1) * 2;
            const int r = wr * 32 + m * 16 + (lane >> 2) + ((j & 1) ? 8 : 0);
            long grow = (long)tile * 64 + r;
            if (grow < M) {
                __half* crow = C + grow * 128 + wc * 32 + (lane & 3) * 2;
                #pragma unroll
                for (int nb = 0; nb < 4; nb++)
                    *(__half2*)(crow + nb * 8) =
                        __floats2half2_rn(acc[m][nb][cp], acc[m][nb][cp + 1]);
            }
        }
        __syncthreads();
        cur ^= 1;
    }
}

// ---------------------------------------------------------------------------
// ew GEMM + fused DistMult: 128-row tiles, 1 CTA/SM, cp.async gather staging.
// ---------------------------------------------------------------------------
__global__ __launch_bounds__(256, 1)
void gemm_ew_kernel(const float* __restrict__ A, const float* __restrict__ W,
                    float* __restrict__ C, int M,
                    const void* __restrict__ eidx,
                    const __half* __restrict__ axw_h,
                    const float* __restrict__ tcl,
                    const float* __restrict__ lw,
                    float* __restrict__ scores) {
    constexpr uint32_t OFF_A   = 32768;
    constexpr uint32_t OFF_RED = OFF_A + 65536;
    constexpr uint32_t OFF_G   = OFF_RED + 2048;
    constexpr uint32_t GPITCH  = 272;

    extern __shared__ __align__(128) char smem[];
    const uint32_t sb = smem_u32(smem);
    const int tid = threadIdx.x, lane = tid & 31, wid = tid >> 5;
    const int wr = wid & 3, wc = wid >> 2;

    for (int p = tid; p < 128 * 64; p += 256) {
        int k = p >> 6, n = (p & 63) * 2;
        float2 wv = *(const float2*)(W + (long)k * 128 + n);
        __half2 hp = __floats2half2_rn(wv.x, wv.y);
        uint32_t off = (uint32_t)k * 256 +
                       ((((uint32_t)n >> 3) ^ ((uint32_t)k & 7)) << 4) + ((n & 7) << 1);
        *(__half2*)(smem + off) = hp;
    }

    const float lwv = lw[0];
    const int ntiles = (M + 127) >> 7;
    const int G = gridDim.x;
    float2 pref[32];

    auto prefetch = [&](int t) {
        #pragma unroll
        for (int i = 0; i < 32; i++) {
            int p = i * 256 + tid;
            int r = p >> 6, pc = p & 63;
            long row = (long)t * 128 + r;
            float2 v = make_float2(0.f, 0.f);
            if (row < M) v = __ldcs((const float2*)(A + row * 128l + pc * 2));
            pref[i] = v;
        }
    };
    auto store_buf = [&](int b) {
        #pragma unroll
        for (int i = 0; i < 32; i++) {
            int p = i * 256 + tid;
            int r = p >> 6, col = (p & 63) * 2;
            __half2 hp = __floats2half2_rn(pref[i].x, pref[i].y);
            uint32_t off = (uint32_t)r * 256 +
                           ((((uint32_t)col >> 3) ^ ((uint32_t)r & 7)) << 4) +
                           ((col & 7) << 1);
            *(__half2*)(smem + OFF_A + (uint32_t)b * 32768 + off) = hp;
        }
    };

    int tile = blockIdx.x;
    if (tile < ntiles) {
        prefetch(tile);
        store_buf(0);
        if (tile + G < ntiles) prefetch(tile + G);
    }
    __syncthreads();

    int cur = 0, rcur = 0;
    for (; tile < ntiles; tile += G) {
        {
            long e = (long)tile * 128 + (tid & 127);
            long idx = ld_idx(eidx, (tid < 128) ? e : (long)E_EDGES + e);
            const char* srcp = (const char*)(axw_h + idx * 128);
            uint32_t dstp = sb + OFF_G + (uint32_t)tid * GPITCH;
            #pragma unroll
            for (int c = 0; c < 16; c++)
                cp_async16(dstp + c * 16, srcp + c * 16);
            asm volatile("cp.async.commit_group;" ::: "memory");
        }

        float acc[2][8][4];
        #pragma unroll
        for (int m = 0; m < 2; m++)
            #pragma unroll
            for (int nb = 0; nb < 8; nb++)
                #pragma unroll
                for (int c = 0; c < 4; c++) acc[m][nb][c] = 0.f;

        if (tile + G < ntiles) store_buf(cur ^ 1);
        if (tile + 2 * G < ntiles) prefetch(tile + 2 * G);

        const uint32_t abase = sb + OFF_A + (uint32_t)cur * 32768;
        #pragma unroll
        for (int s = 0; s < 8; s++) {
            uint32_t a[2][4];
            #pragma unroll
            for (int m = 0; m < 2; m++) {
                uint32_t r = (uint32_t)(wr * 32 + m * 16 + (lane & 15));
                uint32_t ch = (uint32_t)(s * 2 + (lane >> 4));
                ldsm_x4(a[m], abase + r * 256 + (((ch ^ (r & 7)) << 4)));
            }
            uint32_t bh[4][4];
            #pragma unroll
            for (int p4 = 0; p4 < 4; p4++) {
                uint32_t k = (uint32_t)(s * 16 + (lane & 15));
                uint32_t nch = (uint32_t)(wc * 8 + p4 * 2 + (lane >> 4));
                ldsm_x4t(bh[p4], sb + k * 256 + (((nch ^ (k & 7)) << 4)));
            }
            #pragma unroll
            for (int m = 0; m < 2; m++)
                #pragma unroll
                for (int p4 = 0; p4 < 4; p4++)
                    #pragma unroll
                    for (int h = 0; h < 2; h++)
                        mma_f16(acc[m][p4 * 2 + h], a[m], &bh[p4][2 * h]);
        }

        asm volatile("cp.async.wait_group 0;" ::: "memory");
        __syncthreads();

        float* red = (float*)(smem + OFF_RED + (uint32_t)rcur * 1024);
        #pragma unroll
        for (int j = 0; j < 4; j++) {
            const int m = j >> 1, cp = (j & 1) * 2;
            const int r = r0_expr(wr, lane) + j * 8;
            long grow = (long)tile * 128 + r;
            if (grow < M) {
                float* crow = C + grow * 128 + wc * 64 + (lane & 3) * 2;
                const __half2* hq = (const __half2*)(smem + OFF_G + (uint32_t)r * GPITCH
                                                     + (uint32_t)wc * 128) + (lane & 3);
                const __half2* tq = (const __half2*)(smem + OFF_G
                                                     + (uint32_t)(128 + r) * GPITCH
                                                     + (uint32_t)wc * 128) + (lane & 3);
                float part = 0.f;
                #pragma unroll
                for (int nb = 0; nb < 8; nb++) {
                    float2 v = make_float2(acc[m][nb][cp], acc[m][nb][cp + 1]);
                    __stcs((float2*)(crow + nb * 8), v);
                    float2 h2 = __half22float2(hq[nb * 4]);
                    float2 t2 = __half22float2(tq[nb * 4]);
                    part = fmaf(v.x * h2.x, t2.x, part);
                    part = fmaf(v.y * h2.y, t2.y, part);
                }
                part += __shfl_xor_sync(0xFFFFFFFFu, part, 1);
                part += __shfl_xor_sync(0xFFFFFFFFu, part, 2);
                if ((lane & 3) == 0) red[wc * 128 + r] = part;
            }
        }
        __syncthreads();
        if (tid < 128) {
            long g2 = (long)tile * 128 + tid;
            scores[g2] = (red[tid] + red[128 + tid]) * tcl[g2] * lwv;
        }
        cur ^= 1; rcur ^= 1;
    }
}

// ---------------------------------------------------------------------------
// Launch
// ---------------------------------------------------------------------------
extern "C" void kernel_launch(void* const* d_in, const int* in_sizes, int n_in,
                              void* d_out, int out_size) {
    const float* x    = (const float*)d_in[0];   // [N, 256]
    const float* ea   = (const float*)d_in[1];   // [E, 128]
    const float* tc   = (const float*)d_in[2];   // [E]
    const float* wn   = (const float*)d_in[3];   // [256, 128]
    const float* we   = (const float*)d_in[4];   // [128, 128]
    const float* lw   = (const float*)d_in[5];   // [1]
    const void*  eidx = d_in[6];                 // [2, E] int32 or int64

    float* out    = (float*)d_out;
    float* axw    = out;                               // [N, 128]
    float* ew     = out + (long)N_NODES * 128;         // [E, 128]
    float* scores = ew + (long)E_EDGES * 128;          // [E]

    __half* xwh;   cudaGetSymbolAddress((void**)&xwh, g_xw_h);
    __half* axw_h; cudaGetSymbolAddress((void**)&axw_h, g_axw_h);

    const int SMEM_XW = 256 * 256 + 32768;                      // 98304
    const int SMEM_EW = 32768 + 65536 + 2048 + 256 * 272;       // 169984
    cudaFuncSetAttribute(gemm_xw_kernel,
                         cudaFuncAttributeMaxDynamicSharedMemorySize, SMEM_XW);
    cudaFuncSetAttribute(gemm_ew_kernel,
                         cudaFuncAttributeMaxDynamicSharedMemorySize, SMEM_EW);

    // 1) dtype detection + zero degree counters
    detect_zero_kernel<<<(N_NODES + 255) / 256, 256>>>(eidx);

    // 2) xw = x @ Wn (fp16 out)
    gemm_xw_kernel<<<304, 256, SMEM_XW>>>(x, wn, xwh, N_NODES);

    // 3) CSR build: histogram -> scan -> fill
    hist_kernel<<<(E_EDGES + 255) / 256, 256>>>(eidx);
    scan_kernel<<<1, 1024>>>();
    fill_kernel<<<(E_EDGES + 255) / 256, 256>>>(eidx);

    // 4) aggregate: axw (fp32) + fp16 shadow, no atomics, no zero-init
    {
        long warps = N_NODES;
        int blocks = (int)((warps * 32 + 255) / 256);
        aggregate_kernel<<<blocks, 256>>>(xwh, axw, axw_h);
    }

    // 5) ew = edge_attr @ We + fused DistMult (128-row tiles, cp.async gathers)
    gemm_ew_kernel<<<152, 256, SMEM_EW>>>(ea, we, ew, E_EDGES, eidx, axw_h,
                                          tc, lw, scores);
}

// round 17
// speedup vs baseline: 1.2937x; 1.2937x over previous
#include <cuda_runtime.h>
#include <cuda_fp16.h>
#include <cstdint>

#define N_NODES 100000
#define E_EDGES 640000
#define NBLK    ((N_NODES + 255) / 256)   // 391

// ---------------------------------------------------------------------------
// Global scratch
// ---------------------------------------------------------------------------
__device__ __half g_xw_h[(size_t)N_NODES * 128];   // x @ Wn (fp16 storage)
__device__ __half g_axw_h[(size_t)N_NODES * 128];  // fp16 shadow of axw
__device__ int    g_idx64;                          // edge_index dtype flag
__device__ int    g_cnt[N_NODES];                   // per-dst degree
__device__ int    g_off[N_NODES];                   // exclusive offsets -> ends
__device__ int    g_bucket[E_EDGES];                // src ids grouped by dst
__device__ int    g_bsum[NBLK];                     // per-block count sums
__device__ int    g_boff[NBLK];                     // exclusive block offsets

// ---------------------------------------------------------------------------
// Helpers
// ---------------------------------------------------------------------------
__device__ __forceinline__ uint32_t smem_u32(const void* p) {
    uint32_t a;
    asm("{ .reg .u64 t; cvta.to.shared.u64 t, %1; cvt.u32.u64 %0, t; }"
        : "=r"(a) : "l"(p));
    return a;
}

__device__ __forceinline__ void mma_f16(float* d, const uint32_t* a, const uint32_t* b) {
    asm volatile(
        "mma.sync.aligned.m16n8k16.row.col.f32.f16.f16.f32 "
        "{%0,%1,%2,%3}, {%4,%5,%6,%7}, {%8,%9}, {%0,%1,%2,%3};"
        : "+f"(d[0]), "+f"(d[1]), "+f"(d[2]), "+f"(d[3])
        : "r"(a[0]), "r"(a[1]), "r"(a[2]), "r"(a[3]), "r"(b[0]), "r"(b[1]));
}

__device__ __forceinline__ void ldsm_x4(uint32_t* r, uint32_t addr) {
    asm volatile("ldmatrix.sync.aligned.m8n8.x4.shared.b16 {%0,%1,%2,%3}, [%4];"
                 : "=r"(r[0]), "=r"(r[1]), "=r"(r[2]), "=r"(r[3]) : "r"(addr));
}
__device__ __forceinline__ void ldsm_x4t(uint32_t* r, uint32_t addr) {
    asm volatile("ldmatrix.sync.aligned.m8n8.x4.trans.shared.b16 {%0,%1,%2,%3}, [%4];"
                 : "=r"(r[0]), "=r"(r[1]), "=r"(r[2]), "=r"(r[3]) : "r"(addr));
}

__device__ __forceinline__ void cp_async16(uint32_t smem_dst, const void* gmem_src) {
    asm volatile("cp.async.ca.shared.global [%0], [%1], 16;"
                 :: "r"(smem_dst), "l"(gmem_src) : "memory");
}

__device__ __forceinline__ int r0_expr(int wr, int lane) { return wr * 32 + (lane >> 2); }

// ---------------------------------------------------------------------------
// detect idx dtype + zero the degree counters
// ---------------------------------------------------------------------------
__global__ __launch_bounds__(256)
void detect_zero_kernel(const void* __restrict__ eidx) {
    int i = blockIdx.x * blockDim.x + threadIdx.x;
    if (i < N_NODES) g_cnt[i] = 0;
    if (i == 0) {
        const unsigned long long* p = (const unsigned long long*)eidx;
        int ok = 1;
        #pragma unroll 1
        for (int j = 0; j < 64; j++)
            if (p[j] >= (unsigned long long)N_NODES) { ok = 0; break; }
        g_idx64 = ok;
    }
}

__device__ __forceinline__ long ld_idx(const void* __restrict__ p, long i) {
    if (g_idx64) return (long)((const long long*)p)[i];
    return (long)((const int*)p)[i];
}

// ---------------------------------------------------------------------------
// CSR build: histogram -> 3-phase scan -> fill
// ---------------------------------------------------------------------------
__global__ __launch_bounds__(256)
void hist_kernel(const void* __restrict__ eidx) {
    int e = blockIdx.x * blockDim.x + threadIdx.x;
    if (e < E_EDGES) {
        int dst = (int)ld_idx(eidx, (long)E_EDGES + e);
        atomicAdd(&g_cnt[dst], 1);
    }
}

// phase 1: per-block sum of 256 counts
__global__ __launch_bounds__(256)
void blocksum_kernel() {
    __shared__ int sh[8];
    int i = blockIdx.x * 256 + threadIdx.x;
    int v = (i < N_NODES) ? g_cnt[i] : 0;
    #pragma unroll
    for (int o = 16; o > 0; o >>= 1) v += __shfl_xor_sync(0xFFFFFFFFu, v, o);
    if ((threadIdx.x & 31) == 0) sh[threadIdx.x >> 5] = v;
    __syncthreads();
    if (threadIdx.x == 0) {
        int s = 0;
        #pragma unroll
        for (int w = 0; w < 8; w++) s += sh[w];
        g_bsum[blockIdx.x] = s;
    }
}

// phase 2: exclusive scan of the 391 block sums (one small block)
__global__ __launch_bounds__(512)
void scanb_kernel() {
    __shared__ int part[512];
    int t = threadIdx.x;
    part[t] = (t < NBLK) ? g_bsum[t] : 0;
    __syncthreads();
    for (int d = 1; d < 512; d <<= 1) {
        int v = (t >= d) ? part[t - d] : 0;
        __syncthreads();
        part[t] += v;
        __syncthreads();
    }
    if (t < NBLK) g_boff[t] = (t == 0) ? 0 : part[t - 1];
}

// phase 3: block-local exclusive scan + block offset -> g_off
__global__ __launch_bounds__(256)
void offsets_kernel() {
    __shared__ int part[256];
    int i = blockIdx.x * 256 + threadIdx.x;
    int t = threadIdx.x;
    int v = (i < N_NODES) ? g_cnt[i] : 0;
    part[t] = v;
    __syncthreads();
    for (int d = 1; d < 256; d <<= 1) {
        int u = (t >= d) ? part[t - d] : 0;
        __syncthreads();
        part[t] += u;
        __syncthreads();
    }
    if (i < N_NODES) g_off[i] = part[t] - v + g_boff[blockIdx.x];
}

// bucket[pos] = src, grouped by dst; g_off becomes per-dst END offsets
__global__ __launch_bounds__(256)
void fill_kernel(const void* __restrict__ eidx) {
    int e = blockIdx.x * blockDim.x + threadIdx.x;
    if (e < E_EDGES) {
        int src = (int)ld_idx(eidx, e);
        int dst = (int)ld_idx(eidx, (long)E_EDGES + e);
        int pos = atomicAdd(&g_off[dst], 1);
        g_bucket[pos] = src;
    }
}

// ---------------------------------------------------------------------------
// Aggregate: warp per node; sum fp16 xw rows in fp32; write axw + shadow.
// ---------------------------------------------------------------------------
__global__ __launch_bounds__(256)
void aggregate_kernel(const __half* __restrict__ xwh,
                      float* __restrict__ axw, __half* __restrict__ shadow) {
    int w = (blockIdx.x * blockDim.x + threadIdx.x) >> 5;
    int lane = threadIdx.x & 31;
    if (w >= N_NODES) return;
    int n = g_cnt[w];
    int start = g_off[w] - n;          // off holds ends after fill
    float a0 = 0.f, a1 = 0.f, a2 = 0.f, a3 = 0.f;
    int j = 0;
    for (; j + 4 <= n; j += 4) {
        int s0 = g_bucket[start + j + 0];
        int s1 = g_bucket[start + j + 1];
        int s2 = g_bucket[start + j + 2];
        int s3 = g_bucket[start + j + 3];
        uint2 r0 = *(const uint2*)(xwh + (long)s0 * 128 + lane * 4);
        uint2 r1 = *(const uint2*)(xwh + (long)s1 * 128 + lane * 4);
        uint2 r2 = *(const uint2*)(xwh + (long)s2 * 128 + lane * 4);
        uint2 r3 = *(const uint2*)(xwh + (long)s3 * 128 + lane * 4);
        float2 f;
        f = __half22float2(*(__half2*)&r0.x); a0 += f.x; a1 += f.y;
        f = __half22float2(*(__half2*)&r0.y); a2 += f.x; a3 += f.y;
        f = __half22float2(*(__half2*)&r1.x); a0 += f.x; a1 += f.y;
        f = __half22float2(*(__half2*)&r1.y); a2 += f.x; a3 += f.y;
        f = __half22float2(*(__half2*)&r2.x); a0 += f.x; a1 += f.y;
        f = __half22float2(*(__half2*)&r2.y); a2 += f.x; a3 += f.y;
        f = __half22float2(*(__half2*)&r3.x); a0 += f.x; a1 += f.y;
        f = __half22float2(*(__half2*)&r3.y); a2 += f.x; a3 += f.y;
    }
    for (; j < n; j++) {
        int s0 = g_bucket[start + j];
        uint2 r0 = *(const uint2*)(xwh + (long)s0 * 128 + lane * 4);
        float2 f;
        f = __half22float2(*(__half2*)&r0.x); a0 += f.x; a1 += f.y;
        f = __half22float2(*(__half2*)&r0.y); a2 += f.x; a3 += f.y;
    }
    *(float4*)(axw + (long)w * 128 + lane * 4) = make_float4(a0, a1, a2, a3);
    uint2 hs;
    *(__half2*)&hs.x = __floats2half2_rn(a0, a1);
    *(__half2*)&hs.y = __floats2half2_rn(a2, a3);
    *(uint2*)(shadow + (long)w * 128 + lane * 4) = hs;
}

// ---------------------------------------------------------------------------
// xw GEMM: 64-row tiles, 2 CTAs/SM, fp16 output.
// ---------------------------------------------------------------------------
__global__ __launch_bounds__(256, 2)
void gemm_xw_kernel(const float* __restrict__ A, const float* __restrict__ W,
                    __half* __restrict__ C, int M) {
    constexpr int K = 256;
    constexpr int KCH = 2;
    constexpr uint32_t OFF_A = (uint32_t)K * 256;

    extern __shared__ __align__(128) char smem[];
    const uint32_t sb = smem_u32(smem);
    const int tid = threadIdx.x, lane = tid & 31, wid = tid >> 5;
    const int wr = wid & 1, wc = wid >> 1;

    for (int p = tid; p < K * 64; p += 256) {
        int k = p >> 6, n = (p & 63) * 2;
        float2 wv = *(const float2*)(W + (long)k * 128 + n);
        __half2 hp = __floats2half2_rn(wv.x, wv.y);
        uint32_t off = (uint32_t)k * 256 +
                       ((((uint32_t)n >> 3) ^ ((uint32_t)k & 7)) << 4) + ((n & 7) << 1);
        *(__half2*)(smem + off) = hp;
    }

    const int ntiles = (M + 63) >> 6;
    const int G = gridDim.x;
    float2 pref[16];

    auto prefetch = [&](int t, int kc) {
        #pragma unroll
        for (int i = 0; i < 16; i++) {
            int p = i * 256 + tid;
            int r = p >> 6, pc = p & 63;
            long row = (long)t * 64 + r;
            float2 v = make_float2(0.f, 0.f);
            if (row < M) v = __ldcs((const float2*)(A + row * (long)K + kc * 128 + pc * 2));
            pref[i] = v;
        }
    };
    auto store_buf = [&](int b) {
        #pragma unroll
        for (int i = 0; i < 16; i++) {
            int p = i * 256 + tid;
            int r = p >> 6, col = (p & 63) * 2;
            __half2 hp = __floats2half2_rn(pref[i].x, pref[i].y);
            uint32_t off = (uint32_t)r * 256 +
                           ((((uint32_t)col >> 3) ^ ((uint32_t)r & 7)) << 4) +
                           ((col & 7) << 1);
            *(__half2*)(smem + OFF_A + (uint32_t)b * 16384 + off) = hp;
        }
    };

    int tile = blockIdx.x;
    if (tile < ntiles) {
        prefetch(tile, 0);
        store_buf(0);
        prefetch(tile, 1);
    }
    __syncthreads();

    int cur = 0;
    for (; tile < ntiles; tile += G) {
        float acc[2][4][4];
        #pragma unroll
        for (int m = 0; m < 2; m++)
            #pragma unroll
            for (int nb = 0; nb < 4; nb++)
                #pragma unroll
                for (int c = 0; c < 4; c++) acc[m][nb][c] = 0.f;

        for (int kc = 0; kc < KCH; kc++) {
            int nt1 = tile, nkc1 = kc + 1;
            if (nkc1 == KCH) { nkc1 = 0; nt1 = tile + G; }
            if (nt1 < ntiles) store_buf(cur ^ 1);
            int nt2 = nt1, nkc2 = nkc1 + 1;
            if (nkc2 == KCH) { nkc2 = 0; nt2 = nt1 + G; }
            if (nt2 < ntiles) prefetch(nt2, nkc2);

            const uint32_t abase = sb + OFF_A + (uint32_t)cur * 16384;
            #pragma unroll
            for (int s = 0; s < 8; s++) {
                uint32_t a[2][4];
                #pragma unroll
                for (int m = 0; m < 2; m++) {
                    uint32_t r = (uint32_t)(wr * 32 + m * 16 + (lane & 15));
                    uint32_t ch = (uint32_t)(s * 2 + (lane >> 4));
                    ldsm_x4(a[m], abase + r * 256 + (((ch ^ (r & 7)) << 4)));
                }
                uint32_t bh[2][4];
                #pragma unroll
                for (int p4 = 0; p4 < 2; p4++) {
                    uint32_t k = (uint32_t)(kc * 128 + s * 16 + (lane & 15));
                    uint32_t nch = (uint32_t)(wc * 4 + p4 * 2 + (lane >> 4));
                    ldsm_x4t(bh[p4], sb + k * 256 + (((nch ^ (k & 7)) << 4)));
                }
                #pragma unroll
                for (int m = 0; m < 2; m++)
                    #pragma unroll
                    for (int p4 = 0; p4 < 2; p4++)
                        #pragma unroll
                        for (int h = 0; h < 2; h++)
                            mma_f16(acc[m][p4 * 2 + h], a[m], &bh[p4][2 * h]);
            }
            if (kc < KCH - 1) { __syncthreads(); cur ^= 1; }
        }

        #pragma unroll
        for (int j = 0; j < 4; j++) {
            const int m = j >> 1, cp = (j & 1) * 2;
            const int r = wr * 32 + m * 16 + (lane >> 2) + ((j & 1) ? 8 : 0);
            long grow = (long)tile * 64 + r;
            if (grow < M) {
                __half* crow = C + grow * 128 + wc * 32 + (lane & 3) * 2;
                #pragma unroll
                for (int nb = 0; nb < 4; nb++)
                    *(__half2*)(crow + nb * 8) =
                        __floats2half2_rn(acc[m][nb][cp], acc[m][nb][cp + 1]);
            }
        }
        __syncthreads();
        cur ^= 1;
    }
}

// ---------------------------------------------------------------------------
// ew GEMM + fused DistMult: 128-row tiles, 1 CTA/SM, cp.async gather staging.
// ---------------------------------------------------------------------------
__global__ __launch_bounds__(256, 1)
void gemm_ew_kernel(const float* __restrict__ A, const float* __restrict__ W,
                    float* __restrict__ C, int M,
                    const void* __restrict__ eidx,
                    const __half* __restrict__ axw_h,
                    const float* __restrict__ tcl,
                    const float* __restrict__ lw,
                    float* __restrict__ scores) {
    constexpr uint32_t OFF_A   = 32768;
    constexpr uint32_t OFF_RED = OFF_A + 65536;
    constexpr uint32_t OFF_G   = OFF_RED + 2048;
    constexpr uint32_t GPITCH  = 272;

    extern __shared__ __align__(128) char smem[];
    const uint32_t sb = smem_u32(smem);
    const int tid = threadIdx.x, lane = tid & 31, wid = tid >> 5;
    const int wr = wid & 3, wc = wid >> 2;

    for (int p = tid; p < 128 * 64; p += 256) {
        int k = p >> 6, n = (p & 63) * 2;
        float2 wv = *(const float2*)(W + (long)k * 128 + n);
        __half2 hp = __floats2half2_rn(wv.x, wv.y);
        uint32_t off = (uint32_t)k * 256 +
                       ((((uint32_t)n >> 3) ^ ((uint32_t)k & 7)) << 4) + ((n & 7) << 1);
        *(__half2*)(smem + off) = hp;
    }

    const float lwv = lw[0];
    const int ntiles = (M + 127) >> 7;
    const int G = gridDim.x;
    float2 pref[32];

    auto prefetch = [&](int t) {
        #pragma unroll
        for (int i = 0; i < 32; i++) {
            int p = i * 256 + tid;
            int r = p >> 6, pc = p & 63;
            long row = (long)t * 128 + r;
            float2 v = make_float2(0.f, 0.f);
            if (row < M) v = __ldcs((const float2*)(A + row * 128l + pc * 2));
            pref[i] = v;
        }
    };
    auto store_buf = [&](int b) {
        #pragma unroll
        for (int i = 0; i < 32; i++) {
            int p = i * 256 + tid;
            int r = p >> 6, col = (p & 63) * 2;
            __half2 hp = __floats2half2_rn(pref[i].x, pref[i].y);
            uint32_t off = (uint32_t)r * 256 +
                           ((((uint32_t)col >> 3) ^ ((uint32_t)r & 7)) << 4) +
                           ((col & 7) << 1);
            *(__half2*)(smem + OFF_A + (uint32_t)b * 32768 + off) = hp;
        }
    };

    int tile = blockIdx.x;
    if (tile < ntiles) {
        prefetch(tile);
        store_buf(0);
        if (tile + G < ntiles) prefetch(tile + G);
    }
    __syncthreads();

    int cur = 0, rcur = 0;
    for (; tile < ntiles; tile += G) {
        {
            long e = (long)tile * 128 + (tid & 127);
            long idx = ld_idx(eidx, (tid < 128) ? e : (long)E_EDGES + e);
            const char* srcp = (const char*)(axw_h + idx * 128);
            uint32_t dstp = sb + OFF_G + (uint32_t)tid * GPITCH;
            #pragma unroll
            for (int c = 0; c < 16; c++)
                cp_async16(dstp + c * 16, srcp + c * 16);
            asm volatile("cp.async.commit_group;" ::: "memory");
        }

        float acc[2][8][4];
        #pragma unroll
        for (int m = 0; m < 2; m++)
            #pragma unroll
            for (int nb = 0; nb < 8; nb++)
                #pragma unroll
                for (int c = 0; c < 4; c++) acc[m][nb][c] = 0.f;

        if (tile + G < ntiles) store_buf(cur ^ 1);
        if (tile + 2 * G < ntiles) prefetch(tile + 2 * G);

        const uint32_t abase = sb + OFF_A + (uint32_t)cur * 32768;
        #pragma unroll
        for (int s = 0; s < 8; s++) {
            uint32_t a[2][4];
            #pragma unroll
            for (int m = 0; m < 2; m++) {
                uint32_t r = (uint32_t)(wr * 32 + m * 16 + (lane & 15));
                uint32_t ch = (uint32_t)(s * 2 + (lane >> 4));
                ldsm_x4(a[m], abase + r * 256 + (((ch ^ (r & 7)) << 4)));
            }
            uint32_t bh[4][4];
            #pragma unroll
            for (int p4 = 0; p4 < 4; p4++) {
                uint32_t k = (uint32_t)(s * 16 + (lane & 15));
                uint32_t nch = (uint32_t)(wc * 8 + p4 * 2 + (lane >> 4));
                ldsm_x4t(bh[p4], sb + k * 256 + (((nch ^ (k & 7)) << 4)));
            }
            #pragma unroll
            for (int m = 0; m < 2; m++)
                #pragma unroll
                for (int p4 = 0; p4 < 4; p4++)
                    #pragma unroll
                    for (int h = 0; h < 2; h++)
                        mma_f16(acc[m][p4 * 2 + h], a[m], &bh[p4][2 * h]);
        }

        asm volatile("cp.async.wait_group 0;" ::: "memory");
        __syncthreads();

        float* red = (float*)(smem + OFF_RED + (uint32_t)rcur * 1024);
        #pragma unroll
        for (int j = 0; j < 4; j++) {
            const int m = j >> 1, cp = (j & 1) * 2;
            const int r = r0_expr(wr, lane) + j * 8;
            long grow = (long)tile * 128 + r;
            if (grow < M) {
                float* crow = C + grow * 128 + wc * 64 + (lane & 3) * 2;
                const __half2* hq = (const __half2*)(smem + OFF_G + (uint32_t)r * GPITCH
                                                     + (uint32_t)wc * 128) + (lane & 3);
                const __half2* tq = (const __half2*)(smem + OFF_G
                                                     + (uint32_t)(128 + r) * GPITCH
                                                     + (uint32_t)wc * 128) + (lane & 3);
                float part = 0.f;
                #pragma unroll
                for (int nb = 0; nb < 8; nb++) {
                    float2 v = make_float2(acc[m][nb][cp], acc[m][nb][cp + 1]);
                    __stcs((float2*)(crow + nb * 8), v);
                    float2 h2 = __half22float2(hq[nb * 4]);
                    float2 t2 = __half22float2(tq[nb * 4]);
                    part = fmaf(v.x * h2.x, t2.x, part);
                    part = fmaf(v.y * h2.y, t2.y, part);
                }
                part += __shfl_xor_sync(0xFFFFFFFFu, part, 1);
                part += __shfl_xor_sync(0xFFFFFFFFu, part, 2);
                if ((lane & 3) == 0) red[wc * 128 + r] = part;
            }
        }
        __syncthreads();
        if (tid < 128) {
            long g2 = (long)tile * 128 + tid;
            scores[g2] = (red[tid] + red[128 + tid]) * tcl[g2] * lwv;
        }
        cur ^= 1; rcur ^= 1;
    }
}

// ---------------------------------------------------------------------------
// Launch
// ---------------------------------------------------------------------------
extern "C" void kernel_launch(void* const* d_in, const int* in_sizes, int n_in,
                              void* d_out, int out_size) {
    const float* x    = (const float*)d_in[0];   // [N, 256]
    const float* ea   = (const float*)d_in[1];   // [E, 128]
    const float* tc   = (const float*)d_in[2];   // [E]
    const float* wn   = (const float*)d_in[3];   // [256, 128]
    const float* we   = (const float*)d_in[4];   // [128, 128]
    const float* lw   = (const float*)d_in[5];   // [1]
    const void*  eidx = d_in[6];                 // [2, E] int32 or int64

    float* out    = (float*)d_out;
    float* axw    = out;                               // [N, 128]
    float* ew     = out + (long)N_NODES * 128;         // [E, 128]
    float* scores = ew + (long)E_EDGES * 128;          // [E]

    __half* xwh;   cudaGetSymbolAddress((void**)&xwh, g_xw_h);
    __half* axw_h; cudaGetSymbolAddress((void**)&axw_h, g_axw_h);

    const int SMEM_XW = 256 * 256 + 32768;                      // 98304
    const int SMEM_EW = 32768 + 65536 + 2048 + 256 * 272;       // 169984
    cudaFuncSetAttribute(gemm_xw_kernel,
                         cudaFuncAttributeMaxDynamicSharedMemorySize, SMEM_XW);
    cudaFuncSetAttribute(gemm_ew_kernel,
                         cudaFuncAttributeMaxDynamicSharedMemorySize, SMEM_EW);

    // 1) dtype detection + zero degree counters
    detect_zero_kernel<<<NBLK, 256>>>(eidx);

    // 2) xw = x @ Wn (fp16 out)
    gemm_xw_kernel<<<304, 256, SMEM_XW>>>(x, wn, xwh, N_NODES);

    // 3) CSR build: histogram -> 3-phase scan -> fill
    hist_kernel<<<(E_EDGES + 255) / 256, 256>>>(eidx);
    blocksum_kernel<<<NBLK, 256>>>();
    scanb_kernel<<<1, 512>>>();
    offsets_kernel<<<NBLK, 256>>>();
    fill_kernel<<<(E_EDGES + 255) / 256, 256>>>(eidx);

    // 4) aggregate: axw (fp32) + fp16 shadow, no atomics, no zero-init
    {
        long warps = N_NODES;
        int blocks = (int)((warps * 32 + 255) / 256);
        aggregate_kernel<<<blocks, 256>>>(xwh, axw, axw_h);
    }

    // 5) ew = edge_attr @ We + fused DistMult (128-row tiles, cp.async gathers)
    gemm_ew_kernel<<<152, 256, SMEM_EW>>>(ea, we, ew, E_EDGES, eidx, axw_h,
                                          tc, lw, scores);
}